// round 6
// baseline (speedup 1.0000x reference)
#include <cuda_runtime.h>
#include <cuda_bf16.h>

// Problem constants (fixed by setup_inputs): B=8, N=128, T=1024, K=3
#define BB   8
#define NN   128
#define TT   1024
#define VPAD 1152          // T + N - 1 = 1151, rounded up; tail zero-padded
#define ITERS (TT / 256)   // 4

__device__ float g_stdv[BB * VPAD];

__global__ void prep_std_kernel(const float* __restrict__ k) {
    int idx = blockIdx.x * blockDim.x + threadIdx.x;
    if (idx >= BB * VPAD) return;
    int b = idx / VPAD;
    int t = idx - b * VPAD;
    float v = 0.0f;
    if (t < TT) {
        size_t off = ((size_t)(b * BB + b) * NN * TT + t) * 2;  // k_gp[b,b,0,t]
        v = k[off];
    }
    g_stdv[idx] = sqrtf(fmaxf(v, 0.0f));
}

__global__ __launch_bounds__(256) void fused_arc_conv_kernel(
    const float* __restrict__ k,
    const float* __restrict__ leak,
    const float* __restrict__ alpha,
    const float* __restrict__ beta,
    float* __restrict__ out)
{
    __shared__ float s0[TT + 2];
    __shared__ float s1[TT + 2];

    const int row = blockIdx.x;          // 0 .. B*B*N-1, layout (i,j,n)
    const int n   = row & (NN - 1);
    const int ij  = row >> 7;
    const int j   = ij & (BB - 1);
    const int i   = ij >> 3;

    const float a  = fmaxf(leak[0], 0.0f);
    const float w0 = fmaxf(alpha[0], 0.0f);
    const float w1 = fmaxf(alpha[1], 0.0f);
    const float w2 = fmaxf(alpha[2], 0.0f);
    const float bv = fmaxf(beta[0], 0.0f);

    const float PIf      = 3.14159265358979323846f;
    const float one_m    = (1.0f - a) * (1.0f - a);
    const float coef     = 1.0f + a * a;
    const float halfcoef = 0.5f * coef;
    const float inv2pi   = 1.0f / (2.0f * PIf);
    const float RL       = 1.0f - 1e-6f;
    const float EPS      = 1e-12f;
    const bool  fast     = (one_m == 0.0f);

    const float2* __restrict__ krow = reinterpret_cast<const float2*>(k) + (size_t)row * TT;
    float2* __restrict__ orow       = reinterpret_cast<float2*>(out)     + (size_t)row * TT;
    const float* __restrict__ sx = g_stdv + i * VPAD;       // std_x[t]
    const float* __restrict__ sy = g_stdv + j * VPAD + n;   // std_y[t] = stdv_pad[j, n+t]

    const int tid = threadIdx.x;

    // ---------- phase 1: front-batched loads + cheap pointwise ----------
    float2 kv[ITERS];
    float  sxv[ITERS], syv[ITERS];
    #pragma unroll
    for (int it = 0; it < ITERS; ++it) {
        const int t = it * 256 + tid;
        kv[it]  = __ldg(krow + t);
        sxv[it] = __ldg(sx + t);
        syv[it] = __ldg(sy + t);
    }

    float c0r[ITERS], dr[ITERS];
    if (fast) {
        #pragma unroll
        for (int it = 0; it < ITERS; ++it) {
            const float sxy = sxv[it] * syv[it];
            const float lim = RL * sxy;
            c0r[it] = halfcoef * fminf(fmaxf(kv[it].x, -lim), lim);
            dr[it]  = halfcoef * kv[it].y;
        }
    } else {
        #pragma unroll 1
        for (int it = 0; it < ITERS; ++it) {
            const float sxy   = sxv[it] * syv[it];
            const float denom = fmaxf(sxy, EPS);
            float rho = fminf(fmaxf(kv[it].x / denom, -RL), RL);
            const float theta = acosf(rho);
            const float s     = sqrtf(fmaxf(1.0f - rho * rho, 0.0f));
            const float tpart = coef * PIf - one_m * theta;
            c0r[it] = sxy * inv2pi * (one_m * s + rho * tpart);
            dr[it]  = tpart * inv2pi * kv[it].y;
        }
    }

    #pragma unroll
    for (int it = 0; it < ITERS; ++it) {
        const int t = it * 256 + tid;
        s0[t + 1] = c0r[it];
        s1[t + 1] = dr[it];
    }
    if (tid == 0) {
        s0[0] = 0.0f; s1[0] = 0.0f;
        s0[TT + 1] = 0.0f; s1[TT + 1] = 0.0f;
    }
    __syncthreads();

    // ---------- phase 2: 3-tap conv (centers in regs, halos from smem) ----------
    #pragma unroll
    for (int it = 0; it < ITERS; ++it) {
        const int t = it * 256 + tid;
        const float kg = w0 * s0[t] + w1 * c0r[it] + w2 * s0[t + 2];
        const float kn = w0 * s1[t] + w1 * dr[it]  + w2 * s1[t + 2] + kg;
        orow[t] = make_float2(kg + bv, kn + bv);
    }
}

extern "C" void kernel_launch(void* const* d_in, const int* in_sizes, int n_in,
                              void* d_out, int out_size) {
    const float* k     = (const float*)d_in[0];
    const float* leak  = (const float*)d_in[1];
    const float* alpha = (const float*)d_in[2];
    const float* beta  = (const float*)d_in[3];
    float* out = (float*)d_out;

    prep_std_kernel<<<(BB * VPAD + 255) / 256, 256>>>(k);
    fused_arc_conv_kernel<<<BB * BB * NN, 256>>>(k, leak, alpha, beta, out);
}